// round 2
// baseline (speedup 1.0000x reference)
#include <cuda_runtime.h>

#define HID   1024
#define SEQ   4096
#define GRID  128     // RNN persistent CTAs (<= SM count -> co-resident)
#define RTHR  256     // 8 warps -> 8 rows per CTA

// Scratch (device globals; no allocation)
__device__ float        g_emb[(size_t)SEQ * HID];   // normalized embeddings
__device__ float        g_pre[(size_t)SEQ * HID];   // W_hi @ x_t + b
__device__ unsigned int g_cnt[SEQ];                 // per-step barrier counters

// ---------------------------------------------------------------------------
// Kernel A: embedding lookup + L2 normalize; zero barrier counters; out[0]=h0
// grid = SEQ blocks x 256 threads; each thread handles 4 elements (float4)
// ---------------------------------------------------------------------------
__global__ void embed_kernel(const int* __restrict__ src,
                             const float* __restrict__ W,
                             const float* __restrict__ h0,
                             float* __restrict__ out) {
    int t   = blockIdx.x;
    int tid = threadIdx.x;

    const float4* row = (const float4*)(W + (size_t)src[t] * HID);
    float4 v = row[tid];                       // 256 * 4 = 1024 elements
    float  ss = v.x*v.x + v.y*v.y + v.z*v.z + v.w*v.w;

    #pragma unroll
    for (int o = 16; o > 0; o >>= 1)
        ss += __shfl_xor_sync(0xffffffffu, ss, o);

    __shared__ float warp_ss[8];
    __shared__ float s_scale;
    int w = tid >> 5, l = tid & 31;
    if (l == 0) warp_ss[w] = ss;
    __syncthreads();
    if (tid == 0) {
        float tot = 0.f;
        #pragma unroll
        for (int i = 0; i < 8; i++) tot += warp_ss[i];
        float n = fmaxf(sqrtf(tot), 1e-12f);
        s_scale = 1.0f / n;
        g_cnt[t] = 0u;                         // reset barrier slot every replay
    }
    __syncthreads();

    float sc = s_scale;
    float4 o4 = make_float4(v.x*sc, v.y*sc, v.z*sc, v.w*sc);
    ((float4*)g_emb)[(size_t)t * (HID/4) + tid] = o4;

    if (t == 0)   // out row 0 = h0
        ((float4*)out)[tid] = ((const float4*)h0)[tid];
}

// ---------------------------------------------------------------------------
// Kernel B: pre = emb @ W_hi^T + b   (M=4096, N=1024, K=1024)
// 64x64 tile, TK=16, 256 threads, 4x4 micro-tile per thread
// ---------------------------------------------------------------------------
#define TM 64
#define TN 64
#define TK 16
#define SPAD 68   // padded row: 2-way max store conflicts, float4-aligned rows

__global__ __launch_bounds__(256) void gemm_kernel(const float* __restrict__ Whi,
                                                   const float* __restrict__ b) {
    __shared__ float As[TK][SPAD];
    __shared__ float Bs[TK][SPAD];

    int tid = threadIdx.x;           // 0..255
    int tx  = tid & 15;              // 0..15 -> n micro
    int ty  = tid >> 4;              // 0..15 -> m micro
    int m0  = blockIdx.y * TM;
    int n0  = blockIdx.x * TN;
    int lr  = tid >> 2;              // 0..63 tile row
    int lk  = (tid & 3) * 4;         // 0,4,8,12

    float acc[4][4] = {};

    const float* A = g_emb;

    for (int k0 = 0; k0 < HID; k0 += TK) {
        float4 av = *(const float4*)(A   + (size_t)(m0 + lr) * HID + k0 + lk);
        float4 bv = *(const float4*)(Whi + (size_t)(n0 + lr) * HID + k0 + lk);
        As[lk+0][lr] = av.x; As[lk+1][lr] = av.y; As[lk+2][lr] = av.z; As[lk+3][lr] = av.w;
        Bs[lk+0][lr] = bv.x; Bs[lk+1][lr] = bv.y; Bs[lk+2][lr] = bv.z; Bs[lk+3][lr] = bv.w;
        __syncthreads();

        #pragma unroll
        for (int kk = 0; kk < TK; kk++) {
            float4 ra = *(const float4*)&As[kk][ty * 4];
            float4 rb = *(const float4*)&Bs[kk][tx * 4];
            float a[4] = {ra.x, ra.y, ra.z, ra.w};
            float c[4] = {rb.x, rb.y, rb.z, rb.w};
            #pragma unroll
            for (int i = 0; i < 4; i++)
                #pragma unroll
                for (int j = 0; j < 4; j++)
                    acc[i][j] += a[i] * c[j];
        }
        __syncthreads();
    }

    #pragma unroll
    for (int j = 0; j < 4; j++) {
        int n = n0 + tx * 4 + j;
        float bj = b[n];
        #pragma unroll
        for (int i = 0; i < 4; i++) {
            int m = m0 + ty * 4 + i;
            g_pre[(size_t)m * HID + n] = acc[i][j] + bj;
        }
    }
}

// ---------------------------------------------------------------------------
// Kernel C: persistent RNN. 128 CTAs x 256 thr. Row r = blockIdx.x*8 + warp.
// W_hh row slice lives in registers (32 floats/thread). Grid barrier per step
// via per-step RED arrive + acquire poll on g_cnt[s].
// ---------------------------------------------------------------------------
__global__ __launch_bounds__(RTHR) void rnn_kernel(const float* __restrict__ Whh,
                                                   float* __restrict__ out) {
    __shared__ float hs[HID];
    int tid  = threadIdx.x;
    int w    = tid >> 5;
    int lane = tid & 31;
    int row  = blockIdx.x * 8 + w;

    // Load this warp's W_hh row into registers (col = k*32 + lane)
    float wreg[32];
    #pragma unroll
    for (int k = 0; k < 32; k++)
        wreg[k] = Whh[(size_t)row * HID + k * 32 + lane];

    for (int s = 0; s < SEQ; s++) {
        // prefetch this row's pre value (only lane 0 uses it)
        float preval = 0.f;
        if (lane == 0) preval = __ldg(&g_pre[(size_t)s * HID + row]);

        // cooperative load of h_{s} = out[s] into smem (L2-only load)
        float4 hv = __ldcg((const float4*)(out + (size_t)s * HID) + tid);
        ((float4*)hs)[tid] = hv;
        __syncthreads();

        // dot(W_hh[row,:], h)
        float a0 = 0.f, a1 = 0.f, a2 = 0.f, a3 = 0.f;
        #pragma unroll
        for (int k = 0; k < 32; k += 4) {
            a0 += wreg[k+0] * hs[(k+0)*32 + lane];
            a1 += wreg[k+1] * hs[(k+1)*32 + lane];
            a2 += wreg[k+2] * hs[(k+2)*32 + lane];
            a3 += wreg[k+3] * hs[(k+3)*32 + lane];
        }
        float acc = (a0 + a1) + (a2 + a3);
        #pragma unroll
        for (int o = 16; o > 0; o >>= 1)
            acc += __shfl_xor_sync(0xffffffffu, acc, o);

        if (lane == 0) {
            float hn = tanhf(acc + preval);
            __stcg(&out[(size_t)(s+1) * HID + row], hn);
        }

        __syncthreads();              // hs reads done; stores issued

        if (tid == 0) {
            __threadfence();          // publish our row writes (gpu scope)
            atomicAdd(&g_cnt[s], 1u); // result unused -> RED
            unsigned v;
            do {
                asm volatile("ld.acquire.gpu.global.u32 %0, [%1];"
                             : "=r"(v) : "l"(&g_cnt[s]) : "memory");
            } while (v < GRID);
        }
        __syncthreads();              // release all warps into step s+1
    }
}

// ---------------------------------------------------------------------------
extern "C" void kernel_launch(void* const* d_in, const int* in_sizes, int n_in,
                              void* d_out, int out_size) {
    const int*   src = (const int*)  d_in[0];
    const float* W   = (const float*)d_in[1];
    const float* h0  = (const float*)d_in[2];
    const float* Whi = (const float*)d_in[3];
    const float* Whh = (const float*)d_in[4];
    const float* b   = (const float*)d_in[5];
    float* out = (float*)d_out;

    embed_kernel<<<SEQ, 256>>>(src, W, h0, out);

    dim3 gg(HID / TN, SEQ / TM);
    gemm_kernel<<<gg, 256>>>(Whi, b);

    rnn_kernel<<<GRID, RTHR>>>(Whh, out);
}